// round 16
// baseline (speedup 1.0000x reference)
#include <cuda_runtime.h>
#include <cstdint>

// CTC loss, probability-domain DP, per-lane block-float exponents.
// R16: fwd/bwd midpoint split where BOTH halves run the identical R15
// forward inner loop (1 shfl/step, mask-FFMA, proven rescale). The backward
// half exploits CTC time-reversal symmetry: beta == alpha of the problem
// with reversed rows and reversed labels. 1024 warps x 32 chunks instead of
// 512 x 64 -> aggregate DRAM demand ~2x, pushing into the bandwidth wall.
// Combine (R14-verified exact):
//   P = sum_s alpha_255[s]*(beta[s]+beta[s+1]+allow[s+2]*beta[s+2]),
//   beta[u] = alpha'_255[128-u].
// B=512, T=512, C=128, L=64, S=129, blank=127.

#define CTC_B 512
#define CTC_T 512
#define CTC_C 128
#define CTC_L 64
#define CH    8                   // rows per chunk = rescale period
#define RCH   6                   // ring slots per warp (24 KB)
#define WA    4                   // write-ahead distance (chunks)
#define NCHH  (CTC_T / 2 / CH)    // 32 chunks per half
#define WPB   4                   // warps per CTA: 2 batch elems x (fwd,bwd)
#define RING_F (RCH * CH * CTC_C) // 6144 floats per warp ring
#define PUB_F  264                // per-pair publish area (132 vals + 132 exps)
#define SMEM_FLOATS (WPB * RING_F + 2 * PUB_F)
#define SMEM_BYTES  (SMEM_FLOATS * 4)   // 100,416 B

__global__ void __launch_bounds__(WPB * 32, 2) ctc_kernel(
    const int* __restrict__ y_true,
    const float* __restrict__ y_pred,
    float* __restrict__ out)
{
    extern __shared__ float smem[];

    const float EPS = 1e-7f;
    const float LN2 = 0.69314718055994530942f;
    const unsigned FULL = 0xffffffffu;
    const int w    = threadIdx.x >> 5;
    const int lane = threadIdx.x & 31;
    const int pair = w >> 1;                 // batch element within CTA
    const int dir  = w & 1;                  // 0 = forward, 1 = reversed
    const int b    = blockIdx.x * 2 + pair;

    float* ring = smem + w * RING_F;
    float* pubv = smem + WPB * RING_F + pair * PUB_F;   // bwd alpha' values
    float* pube = pubv + 132;                            // bwd exponents

    // Labels: forward uses l_i; reversed uses l'_i = l_{63-i}.
    const int* lrow = y_true + b * CTC_L;
    const int i1 = dir ? (63 - 2 * lane) : (2 * lane);
    const int i3 = dir ? (62 - 2 * lane) : (2 * lane + 1);
    const int ip = dir ? (64 - 2 * lane) : (2 * lane - 1);
    const int lab1 = lrow[i1];
    const int lab3 = lrow[i3];
    const int prev1 = (lane > 0) ? lrow[ip] : -1;
    const float m1 = ((lane > 0) && (lab1 != prev1)) ? 1.0f : 0.0f;
    const float m3 = (lab3 != lab1) ? 1.0f : 0.0f;

    const float* base = y_pred + (size_t)b * CTC_T * CTC_C;
    const unsigned smb = (unsigned)__cvta_generic_to_shared(ring);
    const unsigned lane4 = 4u * lane;

    // Issue one chunk (8 rows). Forward: rows c*8+r; reversed: 511-(c*8+r).
    auto issue_chunk = [&](int c) {
        const unsigned sbase = (unsigned)(c % RCH) * (CH * CTC_C);
#pragma unroll
        for (int r = 0; r < CH; ++r) {
            const int row = dir ? (CTC_T - 1 - (c * CH + r)) : (c * CH + r);
            const float* src = base + (size_t)row * CTC_C + lane4;
            const unsigned dst = smb + (sbase + (unsigned)r * CTC_C + lane4) * 4u;
            asm volatile("cp.async.cg.shared.global [%0], [%1], 16;"
                         :: "r"(dst), "l"(src));
        }
        asm volatile("cp.async.commit_group;");
    };

#pragma unroll
    for (int c = 0; c < WA; ++c) issue_chunk(c);

    // identical R15 state for both directions
    float a0 = (lane == 0) ? 1.0f : 0.0f;
    float a1 = 0.0f, a2 = 0.0f, a3 = 0.0f, a4 = 0.0f;
    int   E  = 0;
    float f  = (lane == 0) ? 0.0f : 1.0f;

    auto do_chunk = [&](int c) {
        const int cb = (c % RCH) * (CH * CTC_C);
        float pb[CH], p1[CH], p3[CH];
#pragma unroll
        for (int j = 0; j < CH; ++j) {
            const int rb = cb + j * CTC_C;
            pb[j] = ring[rb + (CTC_C - 1)] + EPS;
            p1[j] = ring[rb + lab1] + EPS;
            p3[j] = ring[rb + lab3] + EPS;
        }
#pragma unroll
        for (int j = 0; j < CH; ++j) {
            const float am1 = __shfl_up_sync(FULL, a3, 1) * f;
            const float n0 = (a0 + am1) * pb[j];
            const float n1 = fmaf(am1, m1, a1 + a0) * p1[j];
            const float n2 = (a2 + a1) * pb[j];
            const float n3 = fmaf(a1, m3, a3 + a2) * p3[j];
            const float n4 = (a4 + a3) * pb[j];
            a0 = n0; a1 = n1; a2 = n2; a3 = n3; a4 = n4;
        }
        // per-lane power-of-2 rescale (R6-exact)
        float lm = fmaxf(fmaxf(a0, a1), fmaxf(a2, a3));
        lm = fmaxf(lm, a4);
        int e = (int)(__float_as_uint(lm) >> 23) - 127;
        const bool zero = (lm == 0.0f);
        if (zero) e = 0;
        const float sc = __uint_as_float((unsigned)(127 - e) << 23);
        a0 *= sc; a1 *= sc; a2 *= sc; a3 *= sc; a4 *= sc;
        E += e;
        const int Ep = __shfl_up_sync(FULL, E, 1);
        if (zero && lane > 0) E = Ep;
        const int Ep2 = __shfl_up_sync(FULL, E, 1);
        int d = Ep2 - E;
        d = max(-126, min(126, d));
        f = __uint_as_float((unsigned)(127 + d) << 23);
        if (lane == 0) f = 0.0f;
    };

    for (int c = 0; c < NCHH; c += 2) {
        if (c + WA < NCHH) issue_chunk(c + WA);
        else asm volatile("cp.async.commit_group;");
        if (c + WA + 1 < NCHH) issue_chunk(c + WA + 1);
        else asm volatile("cp.async.commit_group;");
        asm volatile("cp.async.wait_group %0;" :: "n"(WA));
        __syncwarp();
        do_chunk(c);
        do_chunk(c + 1);
    }

    // bwd publishes alpha' (normalized values + exponents)
    if (dir) {
        pubv[4 * lane + 0] = a0;  pube[4 * lane + 0] = __int_as_float(E);
        pubv[4 * lane + 1] = a1;  pube[4 * lane + 1] = __int_as_float(E);
        pubv[4 * lane + 2] = a2;  pube[4 * lane + 2] = __int_as_float(E);
        pubv[4 * lane + 3] = a3;  pube[4 * lane + 3] = __int_as_float(E);
        if (lane == 31) { pubv[128] = a4; pube[128] = __int_as_float(E); }
    }
    __syncthreads();

    if (!dir) {
        // combine: beta[u] = pubv[128-u] (in its own lane-frame exponent)
        const float a1n = ((lane < 31) &&
                           (lrow[2 * lane + 2] != lrow[2 * lane + 1])) ? 1.0f : 0.0f;
        const int ib = 127 - 4 * lane;         // index of beta[4l+1]
        const float B1 = pubv[ib];
        const float B2 = pubv[ib - 1];
        const float B3 = pubv[ib - 2];
        const float B4 = pubv[ib - 3];
        const int   eB = __float_as_int(pube[ib]);
        const float BA = pubv[ib + 1];         // beta[4l]
        const int   eA = __float_as_int(pube[ib + 1]);
        const float BC = (lane < 31) ? pubv[ib - 4] : 0.0f;   // beta[4l+5]
        const int   eC = (lane < 31) ? __float_as_int(pube[ib - 4]) : eB;

        int dA = max(-126, min(126, eA - eB));
        int dC = max(-126, min(126, eC - eB));
        const float fA = __uint_as_float((unsigned)(127 + dA) << 23);
        const float fC = __uint_as_float((unsigned)(127 + dC) << 23);

        float contrib =
            a0 * (BA * fA + B1) +
            a1 * (B1 + B2 + m3 * B3) +
            a2 * (B2 + B3) +
            a3 * (B3 + B4 + a1n * (BC * fC));
        if (lane == 31) contrib += a4 * pubv[0];   // s=128 self; same frame as eB

        int e = E + eB;
        int m = e;
#pragma unroll
        for (int o = 16; o; o >>= 1) m = max(m, __shfl_xor_sync(FULL, m, o));
        const int dd = e - m;
        const float sc = (dd < -126) ? 0.0f
                       : __uint_as_float((unsigned)(127 + dd) << 23);
        float tot = contrib * sc;
#pragma unroll
        for (int o = 16; o; o >>= 1) tot += __shfl_xor_sync(FULL, tot, o);

        if (lane == 0) out[b] = -(__logf(tot) + (float)m * LN2);
    }
}

extern "C" void kernel_launch(void* const* d_in, const int* in_sizes, int n_in,
                              void* d_out, int out_size) {
    const int*   y_true = (const int*)d_in[0];
    const float* y_pred = (const float*)d_in[1];
    float*       outp   = (float*)d_out;
    (void)in_sizes; (void)n_in; (void)out_size;

    cudaFuncSetAttribute(ctc_kernel,
                         cudaFuncAttributeMaxDynamicSharedMemorySize, SMEM_BYTES);
    ctc_kernel<<<CTC_B / 2, WPB * 32, SMEM_BYTES>>>(y_true, y_pred, outp);
}